// round 12
// baseline (speedup 1.0000x reference)
#include <cuda_runtime.h>
#include <cuda_bf16.h>
#include <math.h>
#include <stdint.h>
#include <cstdint>

// ---------------- problem constants ----------------
#define BVAL 32
#define CCH 3
#define HH 224
#define WW 224
#define PS 16
#define DIM 768
#define NHEAD 12
#define HDIM 64
#define DEPTH 12
#define MLPD 3072
#define NCLS 1000
#define GH_ 14
#define GW_ 14
#define TT 196
#define PD 768               // patch dim = 16*16*3
#define MTOK (BVAL*TT)       // 6272 token rows

// ---------------- scratch (device globals; no runtime alloc allowed) ----------------
__device__ float g_P  [MTOK*PD];
__device__ float g_h  [MTOK*DIM];
__device__ float g_xn [MTOK*DIM];
__device__ float g_q  [MTOK*DIM];
__device__ float g_k  [MTOK*DIM];
__device__ float g_v  [MTOK*DIM];
__device__ float g_att[MTOK*DIM];
__device__ float g_S  [BVAL*NHEAD*TT*TT];
__device__ float g_m1 [(size_t)MTOK*MLPD];
__device__ float g_pos[TT*DIM];
__device__ float g_Wqkv[3*DEPTH*DIM*DIM];   // [which][l][d][h*64+e]
__device__ float g_pool[BVAL*DIM];

// ---------------- helpers ----------------
__device__ __forceinline__ void cpa16(void* dst, const void* src) {
    uint32_t d = (uint32_t)__cvta_generic_to_shared(dst);
    asm volatile("cp.async.cg.shared.global [%0], [%1], 16;\n" :: "r"(d), "l"(src));
}

// ---------------- prep kernels ----------------

__global__ void patchify_k(const float* __restrict__ x, float* __restrict__ P) {
    int idx = blockIdx.x * blockDim.x + threadIdx.x;
    if (idx >= MTOK * PD) return;
    int bt = idx / PD, pc = idx % PD;
    int c = pc % 3, p2 = (pc / 3) % 16, p1 = pc / 48;
    int b = bt / TT, t = bt % TT;
    int gh = t / GW_, gw = t % GW_;
    P[idx] = x[((b * CCH + c) * HH + gh * PS + p1) * WW + gw * PS + p2];
}

__global__ void pos_k(float* __restrict__ pos) {
    int idx = blockIdx.x * blockDim.x + threadIdx.x;
    if (idx >= TT * DIM) return;
    int t = idx / DIM, d = idx % DIM;
    int q = d / 192, j = d % 192;
    float omega = powf(10000.0f, -(float)j / 191.0f);
    float yv = (float)(t / GW_) * omega;
    float xv = (float)(t % GW_) * omega;
    float v = (q == 0) ? sinf(xv) : (q == 1) ? cosf(xv) : (q == 2) ? sinf(yv) : cosf(yv);
    pos[idx] = v;
}

// pack all three: W[which][l][h][d][e] -> out[which][l][d][h*64+e]
__global__ void pack_qkv3_k(const float* __restrict__ Wq, const float* __restrict__ Wk,
                            const float* __restrict__ Wv, float* __restrict__ out) {
    int idx = blockIdx.x * blockDim.x + threadIdx.x;
    if (idx >= 3 * DEPTH * DIM * DIM) return;
    int which = idx / (DEPTH * DIM * DIM);
    int r = idx % (DEPTH * DIM * DIM);
    int l = r / (DIM * DIM);
    int rr = r % (DIM * DIM);
    int d = rr / DIM, n = rr % DIM;
    int h = n / HDIM, e = n % HDIM;
    const float* W = (which == 0) ? Wq : (which == 1) ? Wk : Wv;
    out[idx] = W[(((size_t)l * NHEAD + h) * DIM + d) * HDIM + e];
}

__global__ void addpos_k(float* __restrict__ h, const float* __restrict__ pos) {
    int idx = blockIdx.x * blockDim.x + threadIdx.x;
    if (idx >= MTOK * DIM) return;
    int bt = idx / DIM, d = idx % DIM;
    int t = bt % TT;
    h[idx] += pos[t * DIM + d];
}

// LayerNorm over D=768; one block (256 thr) per row
__global__ void ln_k(const float* __restrict__ X, const float* __restrict__ g,
                     const float* __restrict__ b, float* __restrict__ Y) {
    int row = blockIdx.x;
    int tid = threadIdx.x;
    const float* xr = X + (size_t)row * DIM;
    float v[3], s = 0.f, s2 = 0.f;
#pragma unroll
    for (int i = 0; i < 3; i++) {
        v[i] = xr[tid + i * 256];
        s += v[i];
        s2 += v[i] * v[i];
    }
#pragma unroll
    for (int o = 16; o; o >>= 1) {
        s  += __shfl_xor_sync(0xffffffffu, s,  o);
        s2 += __shfl_xor_sync(0xffffffffu, s2, o);
    }
    __shared__ float sm[8], sm2[8];
    __shared__ float mu_s, rstd_s;
    int w = tid >> 5, lane = tid & 31;
    if (!lane) { sm[w] = s; sm2[w] = s2; }
    __syncthreads();
    if (tid == 0) {
        float a = 0.f, a2 = 0.f;
        for (int i = 0; i < 8; i++) { a += sm[i]; a2 += sm2[i]; }
        float mu = a / 768.0f;
        float var = a2 / 768.0f - mu * mu;
        mu_s = mu;
        rstd_s = rsqrtf(var + 1e-5f);
    }
    __syncthreads();
    float mu = mu_s, rstd = rstd_s;
#pragma unroll
    for (int i = 0; i < 3; i++) {
        int d = tid + i * 256;
        Y[(size_t)row * DIM + d] = (v[i] - mu) * rstd * g[d] + b[d];
    }
}

// ---------------- optimized fp32 SIMT SGEMM ----------------
// C[M,N] = A[M,K] @ B[K,N], both row-major. Tiles 128x128x16, 256 threads,
// 8x8 per thread. B staged via cp.async, A via register-staged transpose,
// double-buffered smem (32KB), 2 CTAs/SM.
// EPI 0: C = acc (+bias)   EPI 1: C = acc + bias + R   EPI 2: C = gelu(acc + bias)
// Requires M%128==0, N%128==0, K%16==0.

template <int EPI>
__global__ void __launch_bounds__(256, 2)
sgemm2(const float* __restrict__ A, const float* __restrict__ B,
       const float* __restrict__ bias, const float* __restrict__ R,
       float* __restrict__ C, int M, int N, int K) {
    __shared__ float As[2][16][128];
    __shared__ float Bs[2][16][128];

    int tid = threadIdx.x;
    int tx = tid & 15, ty = tid >> 4;

    const float* Ab = A + (size_t)blockIdx.y * 128 * K;
    const float* Bb = B + (size_t)blockIdx.x * 128;

    int ar0 = tid >> 2;            // 0..63 (two rows: ar0, 64+ar0)
    int ac0 = (tid & 3) * 4;       // k offset 0,4,8,12
    int br0 = tid >> 5;            // 0..7 (two rows: br0, 8+br0)
    int bc0 = (tid & 31) * 4;

    float4 aR0, aR1;
    auto ldgA = [&](int k0) {
        aR0 = *(const float4*)(Ab + (size_t)ar0 * K + k0 + ac0);
        aR1 = *(const float4*)(Ab + (size_t)(64 + ar0) * K + k0 + ac0);
    };
    auto stsA = [&](int buf) {
        As[buf][ac0 + 0][ar0] = aR0.x;
        As[buf][ac0 + 1][ar0] = aR0.y;
        As[buf][ac0 + 2][ar0] = aR0.z;
        As[buf][ac0 + 3][ar0] = aR0.w;
        As[buf][ac0 + 0][64 + ar0] = aR1.x;
        As[buf][ac0 + 1][64 + ar0] = aR1.y;
        As[buf][ac0 + 2][64 + ar0] = aR1.z;
        As[buf][ac0 + 3][64 + ar0] = aR1.w;
    };
    auto cpaB = [&](int buf, int k0) {
        cpa16(&Bs[buf][br0][bc0],     Bb + (size_t)(k0 + br0) * N + bc0);
        cpa16(&Bs[buf][8 + br0][bc0], Bb + (size_t)(k0 + 8 + br0) * N + bc0);
    };

    float acc[8][8];
#pragma unroll
    for (int i = 0; i < 8; i++)
#pragma unroll
        for (int j = 0; j < 8; j++) acc[i][j] = 0.f;

    ldgA(0);
    cpaB(0, 0);
    asm volatile("cp.async.commit_group;\n" ::);
    stsA(0);
    asm volatile("cp.async.wait_group 0;\n" ::);
    __syncthreads();

    int nkb = K / 16;
    int buf = 0;
    for (int kb = 0; kb < nkb; ++kb) {
        if (kb + 1 < nkb) {
            ldgA((kb + 1) * 16);
            cpaB(buf ^ 1, (kb + 1) * 16);
            asm volatile("cp.async.commit_group;\n" ::);
        }
#pragma unroll
        for (int kk = 0; kk < 16; kk++) {
            float4 a0 = *(const float4*)&As[buf][kk][ty * 4];
            float4 a1 = *(const float4*)&As[buf][kk][64 + ty * 4];
            float4 b0 = *(const float4*)&Bs[buf][kk][tx * 4];
            float4 b1 = *(const float4*)&Bs[buf][kk][64 + tx * 4];
            float af[8] = {a0.x, a0.y, a0.z, a0.w, a1.x, a1.y, a1.z, a1.w};
            float bf[8] = {b0.x, b0.y, b0.z, b0.w, b1.x, b1.y, b1.z, b1.w};
#pragma unroll
            for (int i = 0; i < 8; i++)
#pragma unroll
                for (int j = 0; j < 8; j++) acc[i][j] += af[i] * bf[j];
        }
        if (kb + 1 < nkb) {
            stsA(buf ^ 1);
            asm volatile("cp.async.wait_group 0;\n" ::);
        }
        __syncthreads();
        buf ^= 1;
    }

#pragma unroll
    for (int i = 0; i < 8; i++) {
        int row = blockIdx.y * 128 + ((i < 4) ? ty * 4 + i : 64 + ty * 4 + i - 4);
#pragma unroll
        for (int j = 0; j < 8; j++) {
            int col = blockIdx.x * 128 + ((j < 4) ? tx * 4 + j : 64 + tx * 4 + j - 4);
            float vv = acc[i][j];
            if (bias) vv += bias[col];
            if (EPI == 1) vv += R[(size_t)row * N + col];
            if (EPI == 2) vv = 0.5f * vv * (1.0f + erff(vv * 0.70710678118654752f));
            C[(size_t)row * N + col] = vv;
        }
    }
}

// ---------------- attention ----------------
__global__ void attn_scores_k(const float* __restrict__ Q, const float* __restrict__ K,
                              float* __restrict__ S) {
    int bh = blockIdx.x;
    int t = blockIdx.y;
    int b = bh / NHEAD, h = bh % NHEAD;
    int tid = threadIdx.x;
    int w = tid >> 5, lane = tid & 31;

    __shared__ float qsh[HDIM];
    __shared__ float sred[7];
    __shared__ float sbro;

    if (tid < HDIM) qsh[tid] = Q[(size_t)(b * TT + t) * DIM + h * HDIM + tid];
    __syncthreads();

    int s = tid;
    float val = -INFINITY;
    if (s < TT) {
        const float* kr = K + (size_t)(b * TT + s) * DIM + h * HDIM;
        float dot = 0.f;
#pragma unroll
        for (int d = 0; d < HDIM; d++) dot += qsh[d] * kr[d];
        val = dot * 0.125f;
    }
    float m = val;
#pragma unroll
    for (int o = 16; o; o >>= 1) m = fmaxf(m, __shfl_xor_sync(0xffffffffu, m, o));
    if (!lane) sred[w] = m;
    __syncthreads();
    if (tid == 0) {
        float mm = sred[0];
        for (int i = 1; i < 7; i++) mm = fmaxf(mm, sred[i]);
        sbro = mm;
    }
    __syncthreads();
    float rowmax = sbro;
    float e = (s < TT) ? expf(val - rowmax) : 0.f;
    float su = e;
#pragma unroll
    for (int o = 16; o; o >>= 1) su += __shfl_xor_sync(0xffffffffu, su, o);
    __syncthreads();
    if (!lane) sred[w] = su;
    __syncthreads();
    if (tid == 0) {
        float ss = 0.f;
        for (int i = 0; i < 7; i++) ss += sred[i];
        sbro = 1.0f / ss;
    }
    __syncthreads();
    if (s < TT) S[((size_t)bh * TT + t) * TT + s] = e * sbro;
}

__global__ void attn_av_k(const float* __restrict__ S, const float* __restrict__ V,
                          float* __restrict__ O) {
    int bh = blockIdx.x, t = blockIdx.y;
    int b = bh / NHEAD, h = bh % NHEAD;
    int tid = threadIdx.x;
    __shared__ float psh[TT];
    for (int s = tid; s < TT; s += 64) psh[s] = S[((size_t)bh * TT + t) * TT + s];
    __syncthreads();
    float acc = 0.f;
    const float* vb = V + (size_t)b * TT * DIM + h * HDIM + tid;
#pragma unroll 4
    for (int s = 0; s < TT; s++) acc += psh[s] * vb[(size_t)s * DIM];
    O[(size_t)(b * TT + t) * DIM + h * HDIM + tid] = acc;
}

// ---------------- pool + head ----------------
__global__ void pool_k(const float* __restrict__ h, float* __restrict__ pool) {
    int idx = blockIdx.x * blockDim.x + threadIdx.x;
    if (idx >= BVAL * DIM) return;
    int b = idx / DIM, d = idx % DIM;
    float s = 0.f;
    const float* hp = h + (size_t)b * TT * DIM + d;
    for (int t = 0; t < TT; t++) s += hp[(size_t)t * DIM];
    pool[idx] = s * (1.0f / 196.0f);
}

__global__ void head_k(const float* __restrict__ pool, const float* __restrict__ W,
                       float* __restrict__ out) {
    int b = blockIdx.x;
    int tid = threadIdx.x;
    __shared__ float pr[DIM];
    for (int i = tid; i < DIM; i += 256) pr[i] = pool[b * DIM + i];
    __syncthreads();
    for (int n = tid; n < NCLS; n += 256) {
        float acc = 0.f;
        for (int k = 0; k < DIM; k++) acc += pr[k] * W[(size_t)k * NCLS + n];
        out[b * NCLS + n] = acc;
    }
}

// ---------------- launch ----------------
extern "C" void kernel_launch(void* const* d_in, const int* in_sizes, int n_in,
                              void* d_out, int out_size) {
    const float* x       = (const float*)d_in[0];
    const float* embed_W = (const float*)d_in[1];
    const float* embed_b = (const float*)d_in[2];
    const float* Wq      = (const float*)d_in[3];
    const float* Wk      = (const float*)d_in[4];
    const float* Wv      = (const float*)d_in[5];
    const float* Wo      = (const float*)d_in[6];
    const float* bo      = (const float*)d_in[7];
    const float* ln1_g   = (const float*)d_in[8];
    const float* ln1_b   = (const float*)d_in[9];
    const float* ln2_g   = (const float*)d_in[10];
    const float* ln2_b   = (const float*)d_in[11];
    const float* W1      = (const float*)d_in[12];
    const float* b1      = (const float*)d_in[13];
    const float* W2      = (const float*)d_in[14];
    const float* b2      = (const float*)d_in[15];
    const float* head_W  = (const float*)d_in[16];
    float* out = (float*)d_out;

    float *P, *h, *xn, *q, *k, *v, *att, *S, *m1, *pos, *wqkv, *pool;
    cudaGetSymbolAddress((void**)&P,    g_P);
    cudaGetSymbolAddress((void**)&h,    g_h);
    cudaGetSymbolAddress((void**)&xn,   g_xn);
    cudaGetSymbolAddress((void**)&q,    g_q);
    cudaGetSymbolAddress((void**)&k,    g_k);
    cudaGetSymbolAddress((void**)&v,    g_v);
    cudaGetSymbolAddress((void**)&att,  g_att);
    cudaGetSymbolAddress((void**)&S,    g_S);
    cudaGetSymbolAddress((void**)&m1,   g_m1);
    cudaGetSymbolAddress((void**)&pos,  g_pos);
    cudaGetSymbolAddress((void**)&wqkv, g_Wqkv);
    cudaGetSymbolAddress((void**)&pool, g_pool);

    dim3 gproj(DIM / 128, MTOK / 128);     // 6 x 49
    dim3 gmlp1(MLPD / 128, MTOK / 128);    // 24 x 49
    dim3 gattn(BVAL * NHEAD, TT);          // 384 x 196

    // launches 1-3 = prep; launch 4 = embed GEMM (this is what ncu captures)
    patchify_k<<<(MTOK * PD + 255) / 256, 256>>>(x, P);
    pos_k<<<(TT * DIM + 255) / 256, 256>>>(pos);
    pack_qkv3_k<<<(3 * DEPTH * DIM * DIM + 255) / 256, 256>>>(Wq, Wk, Wv, wqkv);

    sgemm2<0><<<gproj, 256>>>(P, embed_W, embed_b, nullptr, h, MTOK, DIM, PD);
    addpos_k<<<(MTOK * DIM + 255) / 256, 256>>>(h, pos);

    size_t wsz = (size_t)DIM * DIM;

    for (int l = 0; l < DEPTH; l++) {
        ln_k<<<MTOK, 256>>>(h, ln1_g + l * DIM, ln1_b + l * DIM, xn);
        sgemm2<0><<<gproj, 256>>>(xn, wqkv + (size_t)(0 * DEPTH + l) * wsz,
                                  nullptr, nullptr, q, MTOK, DIM, DIM);
        sgemm2<0><<<gproj, 256>>>(xn, wqkv + (size_t)(1 * DEPTH + l) * wsz,
                                  nullptr, nullptr, k, MTOK, DIM, DIM);
        sgemm2<0><<<gproj, 256>>>(xn, wqkv + (size_t)(2 * DEPTH + l) * wsz,
                                  nullptr, nullptr, v, MTOK, DIM, DIM);
        attn_scores_k<<<gattn, 224>>>(q, k, S);
        attn_av_k<<<gattn, 64>>>(S, v, att);
        sgemm2<1><<<gproj, 256>>>(att, Wo + (size_t)l * wsz, bo + l * DIM, h, h,
                                  MTOK, DIM, DIM);
        ln_k<<<MTOK, 256>>>(h, ln2_g + l * DIM, ln2_b + l * DIM, xn);
        sgemm2<2><<<gmlp1, 256>>>(xn, W1 + (size_t)l * DIM * MLPD, b1 + l * MLPD,
                                  nullptr, m1, MTOK, MLPD, DIM);
        sgemm2<1><<<gproj, 256>>>(m1, W2 + (size_t)l * DIM * MLPD, b2 + l * DIM, h, h,
                                  MTOK, DIM, MLPD);
    }

    pool_k<<<(BVAL * DIM + 255) / 256, 256>>>(h, pool);
    head_k<<<BVAL, 256>>>(pool, head_W, out);
}

// round 13
// speedup vs baseline: 1.4779x; 1.4779x over previous
#include <cuda_runtime.h>
#include <cuda_bf16.h>
#include <math.h>
#include <stdint.h>
#include <cstdint>

// ---------------- problem constants ----------------
#define BVAL 32
#define CCH 3
#define HH 224
#define WW 224
#define PS 16
#define DIM 768
#define NHEAD 12
#define HDIM 64
#define DEPTH 12
#define MLPD 3072
#define NCLS 1000
#define GH_ 14
#define GW_ 14
#define TT 196
#define PD 768               // patch dim = 16*16*3
#define MTOK (BVAL*TT)       // 6272 token rows

#define KVPAD 65             // smem row stride for K/V tiles (conflict-free)

// ---------------- scratch (device globals; no runtime alloc allowed) ----------------
__device__ float g_P  [MTOK*PD];
__device__ float g_h  [MTOK*DIM];
__device__ float g_xn [MTOK*DIM];
__device__ float g_q  [MTOK*DIM];
__device__ float g_k  [MTOK*DIM];
__device__ float g_v  [MTOK*DIM];
__device__ float g_att[MTOK*DIM];
__device__ float g_m1 [(size_t)MTOK*MLPD];
__device__ float g_pos[TT*DIM];
__device__ float g_Wqkv[3*DEPTH*DIM*DIM];   // [which][l][d][h*64+e]
__device__ float g_pool[BVAL*DIM];

// ---------------- helpers ----------------
__device__ __forceinline__ void cpa16(void* dst, const void* src) {
    uint32_t d = (uint32_t)__cvta_generic_to_shared(dst);
    asm volatile("cp.async.cg.shared.global [%0], [%1], 16;\n" :: "r"(d), "l"(src));
}

// ---------------- prep kernels ----------------

__global__ void patchify_k(const float* __restrict__ x, float* __restrict__ P) {
    int idx = blockIdx.x * blockDim.x + threadIdx.x;
    if (idx >= MTOK * PD) return;
    int bt = idx / PD, pc = idx % PD;
    int c = pc % 3, p2 = (pc / 3) % 16, p1 = pc / 48;
    int b = bt / TT, t = bt % TT;
    int gh = t / GW_, gw = t % GW_;
    P[idx] = x[((b * CCH + c) * HH + gh * PS + p1) * WW + gw * PS + p2];
}

__global__ void pos_k(float* __restrict__ pos) {
    int idx = blockIdx.x * blockDim.x + threadIdx.x;
    if (idx >= TT * DIM) return;
    int t = idx / DIM, d = idx % DIM;
    int q = d / 192, j = d % 192;
    float omega = powf(10000.0f, -(float)j / 191.0f);
    float yv = (float)(t / GW_) * omega;
    float xv = (float)(t % GW_) * omega;
    float v = (q == 0) ? sinf(xv) : (q == 1) ? cosf(xv) : (q == 2) ? sinf(yv) : cosf(yv);
    pos[idx] = v;
}

// pack all three: W[which][l][h][d][e] -> out[which][l][d][h*64+e]
__global__ void pack_qkv3_k(const float* __restrict__ Wq, const float* __restrict__ Wk,
                            const float* __restrict__ Wv, float* __restrict__ out) {
    int idx = blockIdx.x * blockDim.x + threadIdx.x;
    if (idx >= 3 * DEPTH * DIM * DIM) return;
    int which = idx / (DEPTH * DIM * DIM);
    int r = idx % (DEPTH * DIM * DIM);
    int l = r / (DIM * DIM);
    int rr = r % (DIM * DIM);
    int d = rr / DIM, n = rr % DIM;
    int h = n / HDIM, e = n % HDIM;
    const float* W = (which == 0) ? Wq : (which == 1) ? Wk : Wv;
    out[idx] = W[(((size_t)l * NHEAD + h) * DIM + d) * HDIM + e];
}

__global__ void addpos_k(float* __restrict__ h, const float* __restrict__ pos) {
    int idx = blockIdx.x * blockDim.x + threadIdx.x;
    if (idx >= MTOK * DIM) return;
    int bt = idx / DIM, d = idx % DIM;
    int t = bt % TT;
    h[idx] += pos[t * DIM + d];
}

// LayerNorm over D=768; one block (256 thr) per row
__global__ void ln_k(const float* __restrict__ X, const float* __restrict__ g,
                     const float* __restrict__ b, float* __restrict__ Y) {
    int row = blockIdx.x;
    int tid = threadIdx.x;
    const float* xr = X + (size_t)row * DIM;
    float v[3], s = 0.f, s2 = 0.f;
#pragma unroll
    for (int i = 0; i < 3; i++) {
        v[i] = xr[tid + i * 256];
        s += v[i];
        s2 += v[i] * v[i];
    }
#pragma unroll
    for (int o = 16; o; o >>= 1) {
        s  += __shfl_xor_sync(0xffffffffu, s,  o);
        s2 += __shfl_xor_sync(0xffffffffu, s2, o);
    }
    __shared__ float sm[8], sm2[8];
    __shared__ float mu_s, rstd_s;
    int w = tid >> 5, lane = tid & 31;
    if (!lane) { sm[w] = s; sm2[w] = s2; }
    __syncthreads();
    if (tid == 0) {
        float a = 0.f, a2 = 0.f;
        for (int i = 0; i < 8; i++) { a += sm[i]; a2 += sm2[i]; }
        float mu = a / 768.0f;
        float var = a2 / 768.0f - mu * mu;
        mu_s = mu;
        rstd_s = rsqrtf(var + 1e-5f);
    }
    __syncthreads();
    float mu = mu_s, rstd = rstd_s;
#pragma unroll
    for (int i = 0; i < 3; i++) {
        int d = tid + i * 256;
        Y[(size_t)row * DIM + d] = (v[i] - mu) * rstd * g[d] + b[d];
    }
}

// ---------------- optimized fp32 SIMT SGEMM (profiled ~50 TF/s) ----------------
template <int EPI>
__global__ void __launch_bounds__(256, 2)
sgemm2(const float* __restrict__ A, const float* __restrict__ B,
       const float* __restrict__ bias, const float* __restrict__ R,
       float* __restrict__ C, int M, int N, int K) {
    __shared__ float As[2][16][128];
    __shared__ float Bs[2][16][128];

    int tid = threadIdx.x;
    int tx = tid & 15, ty = tid >> 4;

    const float* Ab = A + (size_t)blockIdx.y * 128 * K;
    const float* Bb = B + (size_t)blockIdx.x * 128;

    int ar0 = tid >> 2;
    int ac0 = (tid & 3) * 4;
    int br0 = tid >> 5;
    int bc0 = (tid & 31) * 4;

    float4 aR0, aR1;
    auto ldgA = [&](int k0) {
        aR0 = *(const float4*)(Ab + (size_t)ar0 * K + k0 + ac0);
        aR1 = *(const float4*)(Ab + (size_t)(64 + ar0) * K + k0 + ac0);
    };
    auto stsA = [&](int buf) {
        As[buf][ac0 + 0][ar0] = aR0.x;
        As[buf][ac0 + 1][ar0] = aR0.y;
        As[buf][ac0 + 2][ar0] = aR0.z;
        As[buf][ac0 + 3][ar0] = aR0.w;
        As[buf][ac0 + 0][64 + ar0] = aR1.x;
        As[buf][ac0 + 1][64 + ar0] = aR1.y;
        As[buf][ac0 + 2][64 + ar0] = aR1.z;
        As[buf][ac0 + 3][64 + ar0] = aR1.w;
    };
    auto cpaB = [&](int buf, int k0) {
        cpa16(&Bs[buf][br0][bc0],     Bb + (size_t)(k0 + br0) * N + bc0);
        cpa16(&Bs[buf][8 + br0][bc0], Bb + (size_t)(k0 + 8 + br0) * N + bc0);
    };

    float acc[8][8];
#pragma unroll
    for (int i = 0; i < 8; i++)
#pragma unroll
        for (int j = 0; j < 8; j++) acc[i][j] = 0.f;

    ldgA(0);
    cpaB(0, 0);
    asm volatile("cp.async.commit_group;\n" ::);
    stsA(0);
    asm volatile("cp.async.wait_group 0;\n" ::);
    __syncthreads();

    int nkb = K / 16;
    int buf = 0;
    for (int kb = 0; kb < nkb; ++kb) {
        if (kb + 1 < nkb) {
            ldgA((kb + 1) * 16);
            cpaB(buf ^ 1, (kb + 1) * 16);
            asm volatile("cp.async.commit_group;\n" ::);
        }
#pragma unroll
        for (int kk = 0; kk < 16; kk++) {
            float4 a0 = *(const float4*)&As[buf][kk][ty * 4];
            float4 a1 = *(const float4*)&As[buf][kk][64 + ty * 4];
            float4 b0 = *(const float4*)&Bs[buf][kk][tx * 4];
            float4 b1 = *(const float4*)&Bs[buf][kk][64 + tx * 4];
            float af[8] = {a0.x, a0.y, a0.z, a0.w, a1.x, a1.y, a1.z, a1.w};
            float bf[8] = {b0.x, b0.y, b0.z, b0.w, b1.x, b1.y, b1.z, b1.w};
#pragma unroll
            for (int i = 0; i < 8; i++)
#pragma unroll
                for (int j = 0; j < 8; j++) acc[i][j] += af[i] * bf[j];
        }
        if (kb + 1 < nkb) {
            stsA(buf ^ 1);
            asm volatile("cp.async.wait_group 0;\n" ::);
        }
        __syncthreads();
        buf ^= 1;
    }

#pragma unroll
    for (int i = 0; i < 8; i++) {
        int row = blockIdx.y * 128 + ((i < 4) ? ty * 4 + i : 64 + ty * 4 + i - 4);
#pragma unroll
        for (int j = 0; j < 8; j++) {
            int col = blockIdx.x * 128 + ((j < 4) ? tx * 4 + j : 64 + tx * 4 + j - 4);
            float vv = acc[i][j];
            if (bias) vv += bias[col];
            if (EPI == 1) vv += R[(size_t)row * N + col];
            if (EPI == 2) vv = 0.5f * vv * (1.0f + erff(vv * 0.70710678118654752f));
            C[(size_t)row * N + col] = vv;
        }
    }
}

// ---------------- fused attention ----------------
// One block per (b, head). K/V head tiles loaded ONCE into smem.
// 8 warps; each warp owns queries t = warp, warp+8, ... (~25 each):
//   q -> regs, 196 scores lane-parallel over keys, warp softmax,
//   probs -> per-warp smem, AV lane-parallel over dims.
__global__ void __launch_bounds__(256)
attn_fused_k(const float* __restrict__ Q, const float* __restrict__ K,
             const float* __restrict__ V, float* __restrict__ O) {
    extern __shared__ float sm[];
    float* Ks = sm;                    // [196][KVPAD]
    float* Vs = sm + TT * KVPAD;       // [196][KVPAD]
    __shared__ float Ps[8][TT + 4];    // per-warp probs

    int bh = blockIdx.x;
    int b = bh / NHEAD, hd = bh % NHEAD;
    int tid = threadIdx.x;
    int warp = tid >> 5, lane = tid & 31;

    const float* Kbase = K + (size_t)b * TT * DIM + hd * HDIM;
    const float* Vbase = V + (size_t)b * TT * DIM + hd * HDIM;

    // cooperative load of K,V head tiles (196x64 each)
    for (int idx = tid; idx < TT * HDIM; idx += 256) {
        int s = idx >> 6, d = idx & 63;
        Ks[s * KVPAD + d] = Kbase[(size_t)s * DIM + d];
        Vs[s * KVPAD + d] = Vbase[(size_t)s * DIM + d];
    }
    __syncthreads();

    for (int t = warp; t < TT; t += 8) {
        // q for this query -> registers (each lane keeps the full 64)
        const float* qr = Q + (size_t)(b * TT + t) * DIM + hd * HDIM;
        float qv[HDIM];
#pragma unroll
        for (int i = 0; i < HDIM / 4; i++) {
            float4 f = *(const float4*)(qr + i * 4);
            qv[i * 4 + 0] = f.x; qv[i * 4 + 1] = f.y;
            qv[i * 4 + 2] = f.z; qv[i * 4 + 3] = f.w;
        }

        // scores: lane handles s = lane + 32j
        float sc[7];
#pragma unroll
        for (int j = 0; j < 7; j++) {
            int s = lane + 32 * j;
            if (s < TT) {
                const float* kr = Ks + s * KVPAD;
                float dot = 0.f;
#pragma unroll
                for (int d = 0; d < HDIM; d++) dot += qv[d] * kr[d];
                sc[j] = dot * 0.125f;
            } else {
                sc[j] = -INFINITY;
            }
        }
        // softmax across the warp
        float m = sc[0];
#pragma unroll
        for (int j = 1; j < 7; j++) m = fmaxf(m, sc[j]);
#pragma unroll
        for (int o = 16; o; o >>= 1) m = fmaxf(m, __shfl_xor_sync(0xffffffffu, m, o));
        float sum = 0.f;
        float ex[7];
#pragma unroll
        for (int j = 0; j < 7; j++) {
            ex[j] = (sc[j] == -INFINITY) ? 0.f : __expf(sc[j] - m);
            sum += ex[j];
        }
#pragma unroll
        for (int o = 16; o; o >>= 1) sum += __shfl_xor_sync(0xffffffffu, sum, o);
        float inv = 1.0f / sum;
#pragma unroll
        for (int j = 0; j < 7; j++) {
            int s = lane + 32 * j;
            if (s < TT) Ps[warp][s] = ex[j] * inv;
        }
        __syncwarp();

        // AV: lane owns dims d0 = lane, d1 = lane + 32
        float acc0 = 0.f, acc1 = 0.f;
        const float* pw = Ps[warp];
        for (int s = 0; s < TT; s++) {
            float p = pw[s];
            acc0 += p * Vs[s * KVPAD + lane];
            acc1 += p * Vs[s * KVPAD + lane + 32];
        }
        float* orow = O + (size_t)(b * TT + t) * DIM + hd * HDIM;
        orow[lane] = acc0;
        orow[lane + 32] = acc1;
        __syncwarp();
    }
}

// ---------------- pool + head ----------------
__global__ void pool_k(const float* __restrict__ h, float* __restrict__ pool) {
    int idx = blockIdx.x * blockDim.x + threadIdx.x;
    if (idx >= BVAL * DIM) return;
    int b = idx / DIM, d = idx % DIM;
    float s = 0.f;
    const float* hp = h + (size_t)b * TT * DIM + d;
    for (int t = 0; t < TT; t++) s += hp[(size_t)t * DIM];
    pool[idx] = s * (1.0f / 196.0f);
}

__global__ void head_k(const float* __restrict__ pool, const float* __restrict__ W,
                       float* __restrict__ out) {
    int b = blockIdx.x;
    int tid = threadIdx.x;
    __shared__ float pr[DIM];
    for (int i = tid; i < DIM; i += 256) pr[i] = pool[b * DIM + i];
    __syncthreads();
    for (int n = tid; n < NCLS; n += 256) {
        float acc = 0.f;
        for (int k = 0; k < DIM; k++) acc += pr[k] * W[(size_t)k * NCLS + n];
        out[b * NCLS + n] = acc;
    }
}

// ---------------- launch ----------------
extern "C" void kernel_launch(void* const* d_in, const int* in_sizes, int n_in,
                              void* d_out, int out_size) {
    const float* x       = (const float*)d_in[0];
    const float* embed_W = (const float*)d_in[1];
    const float* embed_b = (const float*)d_in[2];
    const float* Wq      = (const float*)d_in[3];
    const float* Wk      = (const float*)d_in[4];
    const float* Wv      = (const float*)d_in[5];
    const float* Wo      = (const float*)d_in[6];
    const float* bo      = (const float*)d_in[7];
    const float* ln1_g   = (const float*)d_in[8];
    const float* ln1_b   = (const float*)d_in[9];
    const float* ln2_g   = (const float*)d_in[10];
    const float* ln2_b   = (const float*)d_in[11];
    const float* W1      = (const float*)d_in[12];
    const float* b1      = (const float*)d_in[13];
    const float* W2      = (const float*)d_in[14];
    const float* b2      = (const float*)d_in[15];
    const float* head_W  = (const float*)d_in[16];
    float* out = (float*)d_out;

    float *P, *h, *xn, *q, *k, *v, *att, *m1, *pos, *wqkv, *pool;
    cudaGetSymbolAddress((void**)&P,    g_P);
    cudaGetSymbolAddress((void**)&h,    g_h);
    cudaGetSymbolAddress((void**)&xn,   g_xn);
    cudaGetSymbolAddress((void**)&q,    g_q);
    cudaGetSymbolAddress((void**)&k,    g_k);
    cudaGetSymbolAddress((void**)&v,    g_v);
    cudaGetSymbolAddress((void**)&att,  g_att);
    cudaGetSymbolAddress((void**)&m1,   g_m1);
    cudaGetSymbolAddress((void**)&pos,  g_pos);
    cudaGetSymbolAddress((void**)&wqkv, g_Wqkv);
    cudaGetSymbolAddress((void**)&pool, g_pool);

    const int ATTN_SMEM = 2 * TT * KVPAD * sizeof(float);   // ~102 KB
    cudaFuncSetAttribute(attn_fused_k, cudaFuncAttributeMaxDynamicSharedMemorySize,
                         ATTN_SMEM);

    dim3 gproj(DIM / 128, MTOK / 128);     // 6 x 49
    dim3 gmlp1(MLPD / 128, MTOK / 128);    // 24 x 49

    // launches 1-3 = prep; launch 4 = embed GEMM (ncu captures launch #4)
    patchify_k<<<(MTOK * PD + 255) / 256, 256>>>(x, P);
    pos_k<<<(TT * DIM + 255) / 256, 256>>>(pos);
    pack_qkv3_k<<<(3 * DEPTH * DIM * DIM + 255) / 256, 256>>>(Wq, Wk, Wv, wqkv);

    sgemm2<0><<<gproj, 256>>>(P, embed_W, embed_b, nullptr, h, MTOK, DIM, PD);
    addpos_k<<<(MTOK * DIM + 255) / 256, 256>>>(h, pos);

    size_t wsz = (size_t)DIM * DIM;

    for (int l = 0; l < DEPTH; l++) {
        ln_k<<<MTOK, 256>>>(h, ln1_g + l * DIM, ln1_b + l * DIM, xn);
        sgemm2<0><<<gproj, 256>>>(xn, wqkv + (size_t)(0 * DEPTH + l) * wsz,
                                  nullptr, nullptr, q, MTOK, DIM, DIM);
        sgemm2<0><<<gproj, 256>>>(xn, wqkv + (size_t)(1 * DEPTH + l) * wsz,
                                  nullptr, nullptr, k, MTOK, DIM, DIM);
        sgemm2<0><<<gproj, 256>>>(xn, wqkv + (size_t)(2 * DEPTH + l) * wsz,
                                  nullptr, nullptr, v, MTOK, DIM, DIM);
        attn_fused_k<<<BVAL * NHEAD, 256, ATTN_SMEM>>>(q, k, v, att);
        sgemm2<1><<<gproj, 256>>>(att, Wo + (size_t)l * wsz, bo + l * DIM, h, h,
                                  MTOK, DIM, DIM);
        ln_k<<<MTOK, 256>>>(h, ln2_g + l * DIM, ln2_b + l * DIM, xn);
        sgemm2<2><<<gmlp1, 256>>>(xn, W1 + (size_t)l * DIM * MLPD, b1 + l * MLPD,
                                  nullptr, m1, MTOK, MLPD, DIM);
        sgemm2<1><<<gproj, 256>>>(m1, W2 + (size_t)l * DIM * MLPD, b2 + l * DIM, h, h,
                                  MTOK, DIM, MLPD);
    }

    pool_k<<<(BVAL * DIM + 255) / 256, 256>>>(h, pool);
    head_k<<<BVAL, 256>>>(pool, head_W, out);
}

// round 15
// speedup vs baseline: 3.6625x; 2.4781x over previous
#include <cuda_runtime.h>
#include <cuda_bf16.h>
#include <math.h>
#include <stdint.h>
#include <cstdint>

// ---------------- problem constants ----------------
#define BVAL 32
#define CCH 3
#define HH 224
#define WW 224
#define PS 16
#define DIM 768
#define NHEAD 12
#define HDIM 64
#define DEPTH 12
#define MLPD 3072
#define NCLS 1000
#define GH_ 14
#define GW_ 14
#define TT 196
#define PD 768               // patch dim = 16*16*3
#define MTOK (BVAL*TT)       // 6272 token rows
#define QKVD (3*DIM)         // 2304

#define KVPAD 65             // smem row stride for K/V tiles (conflict-free)

typedef __nv_bfloat16 bf16;

// ---------------- scratch (device globals; no runtime alloc allowed) ----------------
__device__ float g_h   [MTOK*DIM];
__device__ float g_qkv [(size_t)MTOK*QKVD];
__device__ float g_pos [TT*DIM];
__device__ float g_pool[BVAL*DIM];

// activation bf16 split planes
__device__ bf16 g_PH [MTOK*PD],  g_PL [MTOK*PD];
__device__ bf16 g_xnH[MTOK*DIM], g_xnL[MTOK*DIM];
__device__ bf16 g_atH[MTOK*DIM], g_atL[MTOK*DIM];
__device__ bf16 g_m1H[(size_t)MTOK*MLPD], g_m1L[(size_t)MTOK*MLPD];

// weight bf16 split planes, TRANSPOSED to [N][K]
__device__ bf16 g_embH[DIM*DIM],  g_embL[DIM*DIM];
__device__ bf16 g_qkvH[(size_t)DEPTH*QKVD*DIM], g_qkvL[(size_t)DEPTH*QKVD*DIM]; // [l][n=2304][k]
__device__ bf16 g_woH [DEPTH*DIM*DIM],   g_woL [DEPTH*DIM*DIM];
__device__ bf16 g_w1H [(size_t)DEPTH*DIM*MLPD], g_w1L[(size_t)DEPTH*DIM*MLPD]; // [l][n=3072][k=768]
__device__ bf16 g_w2H [(size_t)DEPTH*DIM*MLPD], g_w2L[(size_t)DEPTH*DIM*MLPD]; // [l][n=768][k=3072]

// ---------------- helpers ----------------
__device__ __forceinline__ void bsplit(float x, bf16& h, bf16& l) {
    h = __float2bfloat16_rn(x);
    l = __float2bfloat16_rn(x - __bfloat162float(h));
}

__device__ __forceinline__ void cpa16(void* dst, const void* src) {
    uint32_t d = (uint32_t)__cvta_generic_to_shared(dst);
    asm volatile("cp.async.cg.shared.global [%0], [%1], 16;\n" :: "r"(d), "l"(src));
}

// ---------------- prep kernels ----------------

__global__ void patchify_split_k(const float* __restrict__ x,
                                 bf16* __restrict__ PH, bf16* __restrict__ PL) {
    int idx = blockIdx.x * blockDim.x + threadIdx.x;
    if (idx >= MTOK * PD) return;
    int bt = idx / PD, pc = idx % PD;
    int c = pc % 3, p2 = (pc / 3) % 16, p1 = pc / 48;
    int b = bt / TT, t = bt % TT;
    int gh = t / GW_, gw = t % GW_;
    float v = x[((b * CCH + c) * HH + gh * PS + p1) * WW + gw * PS + p2];
    bf16 h, l; bsplit(v, h, l);
    PH[idx] = h; PL[idx] = l;
}

__global__ void pos_k(float* __restrict__ pos) {
    int idx = blockIdx.x * blockDim.x + threadIdx.x;
    if (idx >= TT * DIM) return;
    int t = idx / DIM, d = idx % DIM;
    int q = d / 192, j = d % 192;
    float omega = powf(10000.0f, -(float)j / 191.0f);
    float yv = (float)(t / GW_) * omega;
    float xv = (float)(t % GW_) * omega;
    float v = (q == 0) ? sinf(xv) : (q == 1) ? cosf(xv) : (q == 2) ? sinf(yv) : cosf(yv);
    pos[idx] = v;
}

__global__ void addpos_k(float* __restrict__ h, const float* __restrict__ pos) {
    int idx = blockIdx.x * blockDim.x + threadIdx.x;
    if (idx >= MTOK * DIM) return;
    int bt = idx / DIM, d = idx % DIM;
    int t = bt % TT;
    h[idx] += pos[t * DIM + d];
}

// generic transpose+split: in (per z): [K][N] fp32 row-major -> out [N][K] bf16 planes
__global__ void tsplit_k(const float* __restrict__ in, bf16* __restrict__ oh,
                         bf16* __restrict__ ol, int K, int N) {
    __shared__ float t[32][33];
    int z = blockIdx.z;
    const float* inz = in + (size_t)z * K * N;
    bf16* ohz = oh + (size_t)z * K * N;
    bf16* olz = ol + (size_t)z * K * N;
    int n0 = blockIdx.x * 32, k0 = blockIdx.y * 32;
    int tx = threadIdx.x, ty = threadIdx.y;   // 32 x 8
#pragma unroll
    for (int i = 0; i < 4; i++)
        t[ty + 8 * i][tx] = inz[(size_t)(k0 + ty + 8 * i) * N + n0 + tx];
    __syncthreads();
#pragma unroll
    for (int i = 0; i < 4; i++) {
        int n = n0 + ty + 8 * i;
        float v = t[tx][ty + 8 * i];
        bf16 h, l; bsplit(v, h, l);
        ohz[(size_t)n * K + k0 + tx] = h;
        olz[(size_t)n * K + k0 + tx] = l;
    }
}

// qkv pack+transpose+split into combined layout: out[l][n = which*768 + hd*64 + e][k = d]
__global__ void tsplit_qkv_k(const float* __restrict__ Wq, const float* __restrict__ Wk,
                             const float* __restrict__ Wv,
                             bf16* __restrict__ oh, bf16* __restrict__ ol) {
    __shared__ float t[32][33];
    int l = blockIdx.z;
    int n0 = blockIdx.x * 32;       // 0..2272, multiple of 32
    int k0 = blockIdx.y * 32;
    int which = n0 / DIM;
    int nn = n0 % DIM;
    int hd = nn / HDIM, e0 = nn % HDIM;   // e0 in {0,32}
    const float* W = (which == 0) ? Wq : (which == 1) ? Wk : Wv;
    int tx = threadIdx.x, ty = threadIdx.y;
#pragma unroll
    for (int i = 0; i < 4; i++) {
        int d = k0 + ty + 8 * i;
        t[ty + 8 * i][tx] = W[(((size_t)l * NHEAD + hd) * DIM + d) * HDIM + e0 + tx];
    }
    __syncthreads();
    size_t base = (size_t)l * QKVD * DIM;
#pragma unroll
    for (int i = 0; i < 4; i++) {
        int n = n0 + ty + 8 * i;
        float v = t[tx][ty + 8 * i];
        bf16 h, lo; bsplit(v, h, lo);
        oh[base + (size_t)n * DIM + k0 + tx] = h;
        ol[base + (size_t)n * DIM + k0 + tx] = lo;
    }
}

// LayerNorm over D=768; writes split planes
__global__ void ln_k(const float* __restrict__ X, const float* __restrict__ g,
                     const float* __restrict__ b,
                     bf16* __restrict__ YH, bf16* __restrict__ YL) {
    int row = blockIdx.x;
    int tid = threadIdx.x;
    const float* xr = X + (size_t)row * DIM;
    float v[3], s = 0.f, s2 = 0.f;
#pragma unroll
    for (int i = 0; i < 3; i++) {
        v[i] = xr[tid + i * 256];
        s += v[i];
        s2 += v[i] * v[i];
    }
#pragma unroll
    for (int o = 16; o; o >>= 1) {
        s  += __shfl_xor_sync(0xffffffffu, s,  o);
        s2 += __shfl_xor_sync(0xffffffffu, s2, o);
    }
    __shared__ float sm[8], sm2[8];
    __shared__ float mu_s, rstd_s;
    int w = tid >> 5, lane = tid & 31;
    if (!lane) { sm[w] = s; sm2[w] = s2; }
    __syncthreads();
    if (tid == 0) {
        float a = 0.f, a2 = 0.f;
        for (int i = 0; i < 8; i++) { a += sm[i]; a2 += sm2[i]; }
        float mu = a / 768.0f;
        float var = a2 / 768.0f - mu * mu;
        mu_s = mu;
        rstd_s = rsqrtf(var + 1e-5f);
    }
    __syncthreads();
    float mu = mu_s, rstd = rstd_s;
#pragma unroll
    for (int i = 0; i < 3; i++) {
        int d = tid + i * 256;
        float y = (v[i] - mu) * rstd * g[d] + b[d];
        bf16 h, l; bsplit(y, h, l);
        YH[(size_t)row * DIM + d] = h;
        YL[(size_t)row * DIM + d] = l;
    }
}

// ---------------- bf16x3 split tensor-core GEMM (pre-split inputs) ----------------
// C[M,N] = A[M,K] @ B^T stored [N][K].  A planes AH/AL [M][K], B planes BH/BL [N][K].
// Tiles 128x128x16, 8 warps 64x32, 3x mma m16n8k16 per tile, cp.async double buffer.
// EPI 0: C = acc + bias?   EPI 1: C = acc + bias + R   EPI 2: CH/CL = split(gelu(acc+bias))

#define MMA_BF16(d, a, b) asm volatile( \
    "mma.sync.aligned.m16n8k16.row.col.f32.bf16.bf16.f32 " \
    "{%0,%1,%2,%3}, {%4,%5,%6,%7}, {%8,%9}, {%0,%1,%2,%3};\n" \
    : "+f"(d[0]), "+f"(d[1]), "+f"(d[2]), "+f"(d[3]) \
    : "r"(a[0]), "r"(a[1]), "r"(a[2]), "r"(a[3]), "r"(b[0]), "r"(b[1]))

template <int EPI>
__global__ void __launch_bounds__(256, 2)
mma_gemm_bf16(const bf16* __restrict__ AH, const bf16* __restrict__ AL,
              const bf16* __restrict__ BH, const bf16* __restrict__ BL,
              const float* __restrict__ bias, const float* __restrict__ R,
              float* __restrict__ C, bf16* __restrict__ CH, bf16* __restrict__ CL,
              int M, int N, int K) {
    __shared__ __align__(16) bf16 S[2][4][128][24];

    int tid = threadIdx.x;
    int lane = tid & 31, warp = tid >> 5;
    int wm = warp >> 2, wn = warp & 3;
    int q = lane & 3, r4 = lane >> 2;

    const bf16* gsrc[4];
    gsrc[0] = AH + (size_t)blockIdx.y * 128 * K;
    gsrc[1] = AL + (size_t)blockIdx.y * 128 * K;
    gsrc[2] = BH + (size_t)blockIdx.x * 128 * K;
    gsrc[3] = BL + (size_t)blockIdx.x * 128 * K;

    int srow = tid >> 1, sh = (tid & 1) * 8;

    float acc[4][4][4];
#pragma unroll
    for (int mt = 0; mt < 4; mt++)
#pragma unroll
        for (int nt = 0; nt < 4; nt++)
#pragma unroll
            for (int i = 0; i < 4; i++) acc[mt][nt][i] = 0.f;

    auto stage = [&](int buf, int k0) {
#pragma unroll
        for (int p = 0; p < 4; p++)
            cpa16(&S[buf][p][srow][sh], gsrc[p] + (size_t)srow * K + k0 + sh);
    };

    stage(0, 0);
    asm volatile("cp.async.commit_group;\n" ::);

    int niter = K / 16;
    int buf = 0;
    for (int it = 0; it < niter; ++it) {
        if (it + 1 < niter) {
            stage(buf ^ 1, (it + 1) * 16);
            asm volatile("cp.async.commit_group;\n" ::);
            asm volatile("cp.async.wait_group 1;\n" ::);
        } else {
            asm volatile("cp.async.wait_group 0;\n" ::);
        }
        __syncthreads();

        const bf16 (*AsH)[24] = S[buf][0];
        const bf16 (*AsL)[24] = S[buf][1];
        const bf16 (*BsH)[24] = S[buf][2];
        const bf16 (*BsL)[24] = S[buf][3];

        uint32_t bh[4][2], bl[4][2];
#pragma unroll
        for (int nt = 0; nt < 4; nt++) {
            int n0 = wn * 32 + nt * 8 + r4;
            bh[nt][0] = *(const uint32_t*)&BsH[n0][2 * q];
            bh[nt][1] = *(const uint32_t*)&BsH[n0][2 * q + 8];
            bl[nt][0] = *(const uint32_t*)&BsL[n0][2 * q];
            bl[nt][1] = *(const uint32_t*)&BsL[n0][2 * q + 8];
        }
#pragma unroll
        for (int mt = 0; mt < 4; mt++) {
            int m0 = wm * 64 + mt * 16 + r4;
            uint32_t ahf[4], alf[4];
            ahf[0] = *(const uint32_t*)&AsH[m0][2 * q];
            ahf[1] = *(const uint32_t*)&AsH[m0 + 8][2 * q];
            ahf[2] = *(const uint32_t*)&AsH[m0][2 * q + 8];
            ahf[3] = *(const uint32_t*)&AsH[m0 + 8][2 * q + 8];
            alf[0] = *(const uint32_t*)&AsL[m0][2 * q];
            alf[1] = *(const uint32_t*)&AsL[m0 + 8][2 * q];
            alf[2] = *(const uint32_t*)&AsL[m0][2 * q + 8];
            alf[3] = *(const uint32_t*)&AsL[m0 + 8][2 * q + 8];
#pragma unroll
            for (int nt = 0; nt < 4; nt++) MMA_BF16(acc[mt][nt], ahf, bh[nt]);
#pragma unroll
            for (int nt = 0; nt < 4; nt++) MMA_BF16(acc[mt][nt], ahf, bl[nt]);
#pragma unroll
            for (int nt = 0; nt < 4; nt++) MMA_BF16(acc[mt][nt], alf, bh[nt]);
        }
        __syncthreads();
        buf ^= 1;
    }

#pragma unroll
    for (int mt = 0; mt < 4; mt++) {
#pragma unroll
        for (int nt = 0; nt < 4; nt++) {
            int col = blockIdx.x * 128 + wn * 32 + nt * 8 + 2 * q;
            float bias0 = bias ? bias[col] : 0.f;
            float bias1 = bias ? bias[col + 1] : 0.f;
#pragma unroll
            for (int half = 0; half < 2; half++) {
                int row = blockIdx.y * 128 + wm * 64 + mt * 16 + r4 + half * 8;
                float v0 = acc[mt][nt][half * 2 + 0] + bias0;
                float v1 = acc[mt][nt][half * 2 + 1] + bias1;
                if (EPI == 1) {
                    const float2 rr = *(const float2*)(R + (size_t)row * N + col);
                    v0 += rr.x; v1 += rr.y;
                }
                if (EPI == 2) {
                    v0 = 0.5f * v0 * (1.0f + erff(v0 * 0.70710678118654752f));
                    v1 = 0.5f * v1 * (1.0f + erff(v1 * 0.70710678118654752f));
                    bf16 h0, l0, h1, l1;
                    bsplit(v0, h0, l0);
                    bsplit(v1, h1, l1);
                    CH[(size_t)row * N + col] = h0;
                    CH[(size_t)row * N + col + 1] = h1;
                    CL[(size_t)row * N + col] = l0;
                    CL[(size_t)row * N + col + 1] = l1;
                } else {
                    float2 o; o.x = v0; o.y = v1;
                    *(float2*)(C + (size_t)row * N + col) = o;
                }
            }
        }
    }
}

// ---------------- fused attention ----------------
// One block per (b, head); reads fp32 combined qkv [row][2304]; K/V head tiles
// loaded once to smem; outputs split bf16 planes for the Wo GEMM.
__global__ void __launch_bounds__(256)
attn_fused_k(const float* __restrict__ QKV, bf16* __restrict__ OH, bf16* __restrict__ OL) {
    extern __shared__ float sm[];
    float* Ks = sm;                    // [196][KVPAD]
    float* Vs = sm + TT * KVPAD;       // [196][KVPAD]
    __shared__ float Ps[8][TT + 4];

    int bh = blockIdx.x;
    int b = bh / NHEAD, hd = bh % NHEAD;
    int tid = threadIdx.x;
    int warp = tid >> 5, lane = tid & 31;

    const float* Kbase = QKV + (size_t)b * TT * QKVD + DIM + hd * HDIM;
    const float* Vbase = QKV + (size_t)b * TT * QKVD + 2 * DIM + hd * HDIM;

    for (int idx = tid; idx < TT * HDIM; idx += 256) {
        int s = idx >> 6, d = idx & 63;
        Ks[s * KVPAD + d] = Kbase[(size_t)s * QKVD + d];
        Vs[s * KVPAD + d] = Vbase[(size_t)s * QKVD + d];
    }
    __syncthreads();

    for (int t = warp; t < TT; t += 8) {
        const float* qr = QKV + (size_t)(b * TT + t) * QKVD + hd * HDIM;
        float qv[HDIM];
#pragma unroll
        for (int i = 0; i < HDIM / 4; i++) {
            float4 f = *(const float4*)(qr + i * 4);
            qv[i * 4 + 0] = f.x; qv[i * 4 + 1] = f.y;
            qv[i * 4 + 2] = f.z; qv[i * 4 + 3] = f.w;
        }

        float sc[7];
#pragma unroll
        for (int j = 0; j < 7; j++) {
            int s = lane + 32 * j;
            if (s < TT) {
                const float* kr = Ks + s * KVPAD;
                float dot = 0.f;
#pragma unroll
                for (int d = 0; d < HDIM; d++) dot += qv[d] * kr[d];
                sc[j] = dot * 0.125f;
            } else {
                sc[j] = -INFINITY;
            }
        }
        float m = sc[0];
#pragma unroll
        for (int j = 1; j < 7; j++) m = fmaxf(m, sc[j]);
#pragma unroll
        for (int o = 16; o; o >>= 1) m = fmaxf(m, __shfl_xor_sync(0xffffffffu, m, o));
        float sum = 0.f;
        float ex[7];
#pragma unroll
        for (int j = 0; j < 7; j++) {
            ex[j] = (sc[j] == -INFINITY) ? 0.f : __expf(sc[j] - m);
            sum += ex[j];
        }
#pragma unroll
        for (int o = 16; o; o >>= 1) sum += __shfl_xor_sync(0xffffffffu, sum, o);
        float inv = 1.0f / sum;
#pragma unroll
        for (int j = 0; j < 7; j++) {
            int s = lane + 32 * j;
            if (s < TT) Ps[warp][s] = ex[j] * inv;
        }
        __syncwarp();

        float acc0 = 0.f, acc1 = 0.f;
        const float* pw = Ps[warp];
        for (int s = 0; s < TT; s++) {
            float p = pw[s];
            acc0 += p * Vs[s * KVPAD + lane];
            acc1 += p * Vs[s * KVPAD + lane + 32];
        }
        size_t obase = (size_t)(b * TT + t) * DIM + hd * HDIM;
        bf16 h0, l0, h1, l1;
        bsplit(acc0, h0, l0);
        bsplit(acc1, h1, l1);
        OH[obase + lane] = h0;
        OH[obase + lane + 32] = h1;
        OL[obase + lane] = l0;
        OL[obase + lane + 32] = l1;
        __syncwarp();
    }
}

// ---------------- pool + head ----------------
__global__ void pool_k(const float* __restrict__ h, float* __restrict__ pool) {
    int idx = blockIdx.x * blockDim.x + threadIdx.x;
    if (idx >= BVAL * DIM) return;
    int b = idx / DIM, d = idx % DIM;
    float s = 0.f;
    const float* hp = h + (size_t)b * TT * DIM + d;
    for (int t = 0; t < TT; t++) s += hp[(size_t)t * DIM];
    pool[idx] = s * (1.0f / 196.0f);
}

__global__ void head_k(const float* __restrict__ pool, const float* __restrict__ W,
                       float* __restrict__ out) {
    int b = blockIdx.x;
    int tid = threadIdx.x;
    __shared__ float pr[DIM];
    for (int i = tid; i < DIM; i += 256) pr[i] = pool[b * DIM + i];
    __syncthreads();
    for (int n = tid; n < NCLS; n += 256) {
        float acc = 0.f;
        for (int k = 0; k < DIM; k++) acc += pr[k] * W[(size_t)k * NCLS + n];
        out[b * NCLS + n] = acc;
    }
}

// ---------------- launch ----------------
extern "C" void kernel_launch(void* const* d_in, const int* in_sizes, int n_in,
                              void* d_out, int out_size) {
    const float* x       = (const float*)d_in[0];
    const float* embed_W = (const float*)d_in[1];
    const float* embed_b = (const float*)d_in[2];
    const float* Wq      = (const float*)d_in[3];
    const float* Wk      = (const float*)d_in[4];
    const float* Wv      = (const float*)d_in[5];
    const float* Wo      = (const float*)d_in[6];
    const float* bo      = (const float*)d_in[7];
    const float* ln1_g   = (const float*)d_in[8];
    const float* ln1_b   = (const float*)d_in[9];
    const float* ln2_g   = (const float*)d_in[10];
    const float* ln2_b   = (const float*)d_in[11];
    const float* W1      = (const float*)d_in[12];
    const float* b1      = (const float*)d_in[13];
    const float* W2      = (const float*)d_in[14];
    const float* b2      = (const float*)d_in[15];
    const float* head_W  = (const float*)d_in[16];
    float* out = (float*)d_out;

    float *h, *qkv, *pos, *pool;
    cudaGetSymbolAddress((void**)&h,    g_h);
    cudaGetSymbolAddress((void**)&qkv,  g_qkv);
    cudaGetSymbolAddress((void**)&pos,  g_pos);
    cudaGetSymbolAddress((void**)&pool, g_pool);

    bf16 *PH, *PL, *xnH, *xnL, *atH, *atL, *m1H, *m1L;
    bf16 *embH, *embL, *qkvH, *qkvL, *woH, *woL, *w1H, *w1L, *w2H, *w2L;
    cudaGetSymbolAddress((void**)&PH,   g_PH);
    cudaGetSymbolAddress((void**)&PL,   g_PL);
    cudaGetSymbolAddress((void**)&xnH,  g_xnH);
    cudaGetSymbolAddress((void**)&xnL,  g_xnL);
    cudaGetSymbolAddress((void**)&atH,  g_atH);
    cudaGetSymbolAddress((void**)&atL,  g_atL);
    cudaGetSymbolAddress((void**)&m1H,  g_m1H);
    cudaGetSymbolAddress((void**)&m1L,  g_m1L);
    cudaGetSymbolAddress((void**)&embH, g_embH);
    cudaGetSymbolAddress((void**)&embL, g_embL);
    cudaGetSymbolAddress((void**)&qkvH, g_qkvH);
    cudaGetSymbolAddress((void**)&qkvL, g_qkvL);
    cudaGetSymbolAddress((void**)&woH,  g_woH);
    cudaGetSymbolAddress((void**)&woL,  g_woL);
    cudaGetSymbolAddress((void**)&w1H,  g_w1H);
    cudaGetSymbolAddress((void**)&w1L,  g_w1L);
    cudaGetSymbolAddress((void**)&w2H,  g_w2H);
    cudaGetSymbolAddress((void**)&w2L,  g_w2L);

    const int ATTN_SMEM = 2 * TT * KVPAD * sizeof(float);   // ~102 KB
    cudaFuncSetAttribute(attn_fused_k, cudaFuncAttributeMaxDynamicSharedMemorySize,
                         ATTN_SMEM);

    dim3 tb(32, 8);
    dim3 gemb(DIM / 128, MTOK / 128);      // 6 x 49
    dim3 gqkv(QKVD / 128, MTOK / 128);     // 18 x 49
    dim3 gproj(DIM / 128, MTOK / 128);     // 6 x 49
    dim3 gmlp1(MLPD / 128, MTOK / 128);    // 24 x 49

    // launches 1-3 = prep; launch 4 = embed split-GEMM (ncu captures launch #4)
    patchify_split_k<<<(MTOK * PD + 255) / 256, 256>>>(x, PH, PL);
    pos_k<<<(TT * DIM + 255) / 256, 256>>>(pos);
    tsplit_k<<<dim3(DIM / 32, PD / 32, 1), tb>>>(embed_W, embH, embL, PD, DIM);

    mma_gemm_bf16<0><<<gemb, 256>>>(PH, PL, embH, embL, embed_b, nullptr,
                                    h, nullptr, nullptr, MTOK, DIM, PD);

    addpos_k<<<(MTOK * DIM + 255) / 256, 256>>>(h, pos);
    tsplit_qkv_k<<<dim3(QKVD / 32, DIM / 32, DEPTH), tb>>>(Wq, Wk, Wv, qkvH, qkvL);
    tsplit_k<<<dim3(DIM / 32, DIM / 32, DEPTH), tb>>>(Wo, woH, woL, DIM, DIM);
    tsplit_k<<<dim3(MLPD / 32, DIM / 32, DEPTH), tb>>>(W1, w1H, w1L, DIM, MLPD);
    tsplit_k<<<dim3(DIM / 32, MLPD / 32, DEPTH), tb>>>(W2, w2H, w2L, MLPD, DIM);

    size_t qwsz = (size_t)QKVD * DIM;
    size_t wsz  = (size_t)DIM * DIM;
    size_t msz  = (size_t)DIM * MLPD;

    for (int l = 0; l < DEPTH; l++) {
        ln_k<<<MTOK, 256>>>(h, ln1_g + l * DIM, ln1_b + l * DIM, xnH, xnL);
        mma_gemm_bf16<0><<<gqkv, 256>>>(xnH, xnL,
            qkvH + (size_t)l * qwsz, qkvL + (size_t)l * qwsz,
            nullptr, nullptr, qkv, nullptr, nullptr, MTOK, QKVD, DIM);
        attn_fused_k<<<BVAL * NHEAD, 256, ATTN_SMEM>>>(qkv, atH, atL);
        mma_gemm_bf16<1><<<gproj, 256>>>(atH, atL,
            woH + (size_t)l * wsz, woL + (size_t)l * wsz,
            bo + l * DIM, h, h, nullptr, nullptr, MTOK, DIM, DIM);
        ln_k<<<MTOK, 256>>>(h, ln2_g + l * DIM, ln2_b + l * DIM, xnH, xnL);
        mma_gemm_bf16<2><<<gmlp1, 256>>>(xnH, xnL,
            w1H + (size_t)l * msz, w1L + (size_t)l * msz,
            b1 + l * MLPD, nullptr, nullptr, m1H, m1L, MTOK, MLPD, DIM);
        mma_gemm_bf16<1><<<gproj, 256>>>(m1H, m1L,
            w2H + (size_t)l * msz, w2L + (size_t)l * msz,
            b2 + l * DIM, h, h, nullptr, nullptr, MTOK, DIM, MLPD);
    }

    pool_k<<<(BVAL * DIM + 255) / 256, 256>>>(h, pool);
    head_k<<<BVAL, 256>>>(pool, head_W, out);
}

// round 16
// speedup vs baseline: 3.8415x; 1.0489x over previous
#include <cuda_runtime.h>
#include <cuda_bf16.h>
#include <math.h>
#include <stdint.h>
#include <cstdint>

// ---------------- problem constants ----------------
#define BVAL 32
#define CCH 3
#define HH 224
#define WW 224
#define PS 16
#define DIM 768
#define NHEAD 12
#define HDIM 64
#define DEPTH 12
#define MLPD 3072
#define NCLS 1000
#define GH_ 14
#define GW_ 14
#define TT 196
#define PD 768               // patch dim = 16*16*3
#define MTOK (BVAL*TT)       // 6272 token rows
#define QKVD (3*DIM)         // 2304

#define KVPAD 65             // smem row stride for K/V tiles (conflict-free)

typedef __nv_bfloat16 bf16;

// ---------------- scratch (device globals; no runtime alloc allowed) ----------------
__device__ float g_h   [MTOK*DIM];
__device__ float g_qkv [(size_t)MTOK*QKVD];
__device__ float g_pos [TT*DIM];
__device__ float g_pool[BVAL*DIM];

// activation bf16 split planes
__device__ bf16 g_PH [MTOK*PD],  g_PL [MTOK*PD];
__device__ bf16 g_xnH[MTOK*DIM], g_xnL[MTOK*DIM];
__device__ bf16 g_atH[MTOK*DIM], g_atL[MTOK*DIM];
__device__ bf16 g_m1H[(size_t)MTOK*MLPD], g_m1L[(size_t)MTOK*MLPD];

// weight bf16 split planes, TRANSPOSED to [N][K]
__device__ bf16 g_embH[DIM*DIM],  g_embL[DIM*DIM];
__device__ bf16 g_qkvH[(size_t)DEPTH*QKVD*DIM], g_qkvL[(size_t)DEPTH*QKVD*DIM]; // [l][n=2304][k]
__device__ bf16 g_woH [DEPTH*DIM*DIM],   g_woL [DEPTH*DIM*DIM];
__device__ bf16 g_w1H [(size_t)DEPTH*DIM*MLPD], g_w1L[(size_t)DEPTH*DIM*MLPD]; // [l][n=3072][k=768]
__device__ bf16 g_w2H [(size_t)DEPTH*DIM*MLPD], g_w2L[(size_t)DEPTH*DIM*MLPD]; // [l][n=768][k=3072]

// ---------------- helpers ----------------
__device__ __forceinline__ void bsplit(float x, bf16& h, bf16& l) {
    h = __float2bfloat16_rn(x);
    l = __float2bfloat16_rn(x - __bfloat162float(h));
}

__device__ __forceinline__ void cpa16s(uint32_t dst, const void* src) {
    asm volatile("cp.async.cg.shared.global [%0], [%1], 16;\n" :: "r"(dst), "l"(src));
}

// ---------------- prep kernels ----------------

__global__ void patchify_split_k(const float* __restrict__ x,
                                 bf16* __restrict__ PH, bf16* __restrict__ PL) {
    int idx = blockIdx.x * blockDim.x + threadIdx.x;
    if (idx >= MTOK * PD) return;
    int bt = idx / PD, pc = idx % PD;
    int c = pc % 3, p2 = (pc / 3) % 16, p1 = pc / 48;
    int b = bt / TT, t = bt % TT;
    int gh = t / GW_, gw = t % GW_;
    float v = x[((b * CCH + c) * HH + gh * PS + p1) * WW + gw * PS + p2];
    bf16 h, l; bsplit(v, h, l);
    PH[idx] = h; PL[idx] = l;
}

__global__ void pos_k(float* __restrict__ pos) {
    int idx = blockIdx.x * blockDim.x + threadIdx.x;
    if (idx >= TT * DIM) return;
    int t = idx / DIM, d = idx % DIM;
    int q = d / 192, j = d % 192;
    float omega = powf(10000.0f, -(float)j / 191.0f);
    float yv = (float)(t / GW_) * omega;
    float xv = (float)(t % GW_) * omega;
    float v = (q == 0) ? sinf(xv) : (q == 1) ? cosf(xv) : (q == 2) ? sinf(yv) : cosf(yv);
    pos[idx] = v;
}

__global__ void addpos_k(float* __restrict__ h, const float* __restrict__ pos) {
    int idx = blockIdx.x * blockDim.x + threadIdx.x;
    if (idx >= MTOK * DIM) return;
    int bt = idx / DIM, d = idx % DIM;
    int t = bt % TT;
    h[idx] += pos[t * DIM + d];
}

// generic transpose+split: in (per z): [K][N] fp32 row-major -> out [N][K] bf16 planes
__global__ void tsplit_k(const float* __restrict__ in, bf16* __restrict__ oh,
                         bf16* __restrict__ ol, int K, int N) {
    __shared__ float t[32][33];
    int z = blockIdx.z;
    const float* inz = in + (size_t)z * K * N;
    bf16* ohz = oh + (size_t)z * K * N;
    bf16* olz = ol + (size_t)z * K * N;
    int n0 = blockIdx.x * 32, k0 = blockIdx.y * 32;
    int tx = threadIdx.x, ty = threadIdx.y;   // 32 x 8
#pragma unroll
    for (int i = 0; i < 4; i++)
        t[ty + 8 * i][tx] = inz[(size_t)(k0 + ty + 8 * i) * N + n0 + tx];
    __syncthreads();
#pragma unroll
    for (int i = 0; i < 4; i++) {
        int n = n0 + ty + 8 * i;
        float v = t[tx][ty + 8 * i];
        bf16 h, l; bsplit(v, h, l);
        ohz[(size_t)n * K + k0 + tx] = h;
        olz[(size_t)n * K + k0 + tx] = l;
    }
}

// qkv pack+transpose+split into combined layout: out[l][n = which*768 + hd*64 + e][k = d]
__global__ void tsplit_qkv_k(const float* __restrict__ Wq, const float* __restrict__ Wk,
                             const float* __restrict__ Wv,
                             bf16* __restrict__ oh, bf16* __restrict__ ol) {
    __shared__ float t[32][33];
    int l = blockIdx.z;
    int n0 = blockIdx.x * 32;
    int k0 = blockIdx.y * 32;
    int which = n0 / DIM;
    int nn = n0 % DIM;
    int hd = nn / HDIM, e0 = nn % HDIM;
    const float* W = (which == 0) ? Wq : (which == 1) ? Wk : Wv;
    int tx = threadIdx.x, ty = threadIdx.y;
#pragma unroll
    for (int i = 0; i < 4; i++) {
        int d = k0 + ty + 8 * i;
        t[ty + 8 * i][tx] = W[(((size_t)l * NHEAD + hd) * DIM + d) * HDIM + e0 + tx];
    }
    __syncthreads();
    size_t base = (size_t)l * QKVD * DIM;
#pragma unroll
    for (int i = 0; i < 4; i++) {
        int n = n0 + ty + 8 * i;
        float v = t[tx][ty + 8 * i];
        bf16 h, lo; bsplit(v, h, lo);
        oh[base + (size_t)n * DIM + k0 + tx] = h;
        ol[base + (size_t)n * DIM + k0 + tx] = lo;
    }
}

// LayerNorm over D=768; writes split planes
__global__ void ln_k(const float* __restrict__ X, const float* __restrict__ g,
                     const float* __restrict__ b,
                     bf16* __restrict__ YH, bf16* __restrict__ YL) {
    int row = blockIdx.x;
    int tid = threadIdx.x;
    const float* xr = X + (size_t)row * DIM;
    float v[3], s = 0.f, s2 = 0.f;
#pragma unroll
    for (int i = 0; i < 3; i++) {
        v[i] = xr[tid + i * 256];
        s += v[i];
        s2 += v[i] * v[i];
    }
#pragma unroll
    for (int o = 16; o; o >>= 1) {
        s  += __shfl_xor_sync(0xffffffffu, s,  o);
        s2 += __shfl_xor_sync(0xffffffffu, s2, o);
    }
    __shared__ float sm[8], sm2[8];
    __shared__ float mu_s, rstd_s;
    int w = tid >> 5, lane = tid & 31;
    if (!lane) { sm[w] = s; sm2[w] = s2; }
    __syncthreads();
    if (tid == 0) {
        float a = 0.f, a2 = 0.f;
        for (int i = 0; i < 8; i++) { a += sm[i]; a2 += sm2[i]; }
        float mu = a / 768.0f;
        float var = a2 / 768.0f - mu * mu;
        mu_s = mu;
        rstd_s = rsqrtf(var + 1e-5f);
    }
    __syncthreads();
    float mu = mu_s, rstd = rstd_s;
#pragma unroll
    for (int i = 0; i < 3; i++) {
        int d = tid + i * 256;
        float y = (v[i] - mu) * rstd * g[d] + b[d];
        bf16 h, l; bsplit(y, h, l);
        YH[(size_t)row * DIM + d] = h;
        YL[(size_t)row * DIM + d] = l;
    }
}

// ---------------- bf16x3 split tensor-core GEMM, 128x256 CTA tile ----------------
// C[M,N] = A[M,K] @ B^T stored [N][K]. Warp tile 64x64 (8 warps = 2x4).
// 3-stage cp.async ring, ONE __syncthreads per K=16 iter.
// Stage layout (halves): AH[128][24] | AL[128][24] | BH[256][24] | BL[256][24]
// EPI 0: C = acc + bias?   EPI 1: C = acc + bias + R   EPI 2: CH/CL = split(gelu(acc+bias))

#define STAGE_H 18432                    // halves per stage (36864 B)
#define GEMM_SMEM (3 * STAGE_H * 2)      // 110592 B

#define MMA_BF16(d, a, b) asm volatile( \
    "mma.sync.aligned.m16n8k16.row.col.f32.bf16.bf16.f32 " \
    "{%0,%1,%2,%3}, {%4,%5,%6,%7}, {%8,%9}, {%0,%1,%2,%3};\n" \
    : "+f"(d[0]), "+f"(d[1]), "+f"(d[2]), "+f"(d[3]) \
    : "r"(a[0]), "r"(a[1]), "r"(a[2]), "r"(a[3]), "r"(b[0]), "r"(b[1]))

template <int EPI>
__global__ void __launch_bounds__(256, 1)
mma_gemm_bf16(const bf16* __restrict__ AH, const bf16* __restrict__ AL,
              const bf16* __restrict__ BH, const bf16* __restrict__ BL,
              const float* __restrict__ bias, const float* __restrict__ R,
              float* __restrict__ C, bf16* __restrict__ CH, bf16* __restrict__ CL,
              int M, int N, int K) {
    extern __shared__ __align__(16) bf16 SMB[];
    uint32_t sbase = (uint32_t)__cvta_generic_to_shared(SMB);

    int tid = threadIdx.x;
    int lane = tid & 31, warp = tid >> 5;
    int wm = warp >> 2, wn = warp & 3;          // 2 x 4 warp grid
    int q = lane & 3, r4 = lane >> 2;

    const bf16* gA[2] = { AH + (size_t)blockIdx.y * 128 * K,
                          AL + (size_t)blockIdx.y * 128 * K };
    const bf16* gB[2] = { BH + (size_t)blockIdx.x * 256 * K,
                          BL + (size_t)blockIdx.x * 256 * K };

    int srow = tid >> 1;                // 0..127
    int sh = (tid & 1) * 8;             // k-half offset

    auto stage_load = [&](int s, int k0) {
        uint32_t sb = sbase + s * (STAGE_H * 2);
#pragma unroll
        for (int p = 0; p < 2; p++) {
            // A plane p at halves offset p*3072
            cpa16s(sb + (p * 3072 + srow * 24 + sh) * 2,
                   gA[p] + (size_t)srow * K + k0 + sh);
            // B plane p at halves offset 6144 + p*6144, rows srow and 128+srow
            cpa16s(sb + (6144 + p * 6144 + srow * 24 + sh) * 2,
                   gB[p] + (size_t)srow * K + k0 + sh);
            cpa16s(sb + (6144 + p * 6144 + (128 + srow) * 24 + sh) * 2,
                   gB[p] + (size_t)(128 + srow) * K + k0 + sh);
        }
    };

    float acc[4][8][4];
#pragma unroll
    for (int mt = 0; mt < 4; mt++)
#pragma unroll
        for (int nt = 0; nt < 8; nt++)
#pragma unroll
            for (int i = 0; i < 4; i++) acc[mt][nt][i] = 0.f;

    int niter = K / 16;
    stage_load(0, 0);
    asm volatile("cp.async.commit_group;\n" ::);
    if (niter > 1) {
        stage_load(1, 16);
        asm volatile("cp.async.commit_group;\n" ::);
    }

    for (int it = 0; it < niter; ++it) {
        int s = it % 3;
        if (it + 1 < niter) {
            asm volatile("cp.async.wait_group 1;\n" ::);
        } else {
            asm volatile("cp.async.wait_group 0;\n" ::);
        }
        __syncthreads();

        const bf16* AsH = SMB + s * STAGE_H;
        const bf16* AsL = AsH + 3072;
        const bf16* BsH = SMB + s * STAGE_H + 6144;
        const bf16* BsL = BsH + 6144;

        uint32_t bh[8][2], bl[8][2];
#pragma unroll
        for (int nt = 0; nt < 8; nt++) {
            int n0 = wn * 64 + nt * 8 + r4;
            bh[nt][0] = *(const uint32_t*)&BsH[n0 * 24 + 2 * q];
            bh[nt][1] = *(const uint32_t*)&BsH[n0 * 24 + 2 * q + 8];
            bl[nt][0] = *(const uint32_t*)&BsL[n0 * 24 + 2 * q];
            bl[nt][1] = *(const uint32_t*)&BsL[n0 * 24 + 2 * q + 8];
        }
#pragma unroll
        for (int mt = 0; mt < 4; mt++) {
            int m0 = wm * 64 + mt * 16 + r4;
            uint32_t ahf[4], alf[4];
            ahf[0] = *(const uint32_t*)&AsH[m0 * 24 + 2 * q];
            ahf[1] = *(const uint32_t*)&AsH[(m0 + 8) * 24 + 2 * q];
            ahf[2] = *(const uint32_t*)&AsH[m0 * 24 + 2 * q + 8];
            ahf[3] = *(const uint32_t*)&AsH[(m0 + 8) * 24 + 2 * q + 8];
            alf[0] = *(const uint32_t*)&AsL[m0 * 24 + 2 * q];
            alf[1] = *(const uint32_t*)&AsL[(m0 + 8) * 24 + 2 * q];
            alf[2] = *(const uint32_t*)&AsL[m0 * 24 + 2 * q + 8];
            alf[3] = *(const uint32_t*)&AsL[(m0 + 8) * 24 + 2 * q + 8];
#pragma unroll
            for (int nt = 0; nt < 8; nt++) MMA_BF16(acc[mt][nt], ahf, bh[nt]);
#pragma unroll
            for (int nt = 0; nt < 8; nt++) MMA_BF16(acc[mt][nt], ahf, bl[nt]);
#pragma unroll
            for (int nt = 0; nt < 8; nt++) MMA_BF16(acc[mt][nt], alf, bh[nt]);
        }

        if (it + 2 < niter) {
            stage_load((it + 2) % 3, (it + 2) * 16);
            asm volatile("cp.async.commit_group;\n" ::);
        }
    }

    // epilogue: per (mt,nt): rows {r4, r4+8}, cols {2q, 2q+1}
#pragma unroll
    for (int mt = 0; mt < 4; mt++) {
#pragma unroll
        for (int nt = 0; nt < 8; nt++) {
            int col = blockIdx.x * 256 + wn * 64 + nt * 8 + 2 * q;
            float bias0 = bias ? bias[col] : 0.f;
            float bias1 = bias ? bias[col + 1] : 0.f;
#pragma unroll
            for (int half = 0; half < 2; half++) {
                int row = blockIdx.y * 128 + wm * 64 + mt * 16 + r4 + half * 8;
                float v0 = acc[mt][nt][half * 2 + 0] + bias0;
                float v1 = acc[mt][nt][half * 2 + 1] + bias1;
                if (EPI == 1) {
                    const float2 rr = *(const float2*)(R + (size_t)row * N + col);
                    v0 += rr.x; v1 += rr.y;
                }
                if (EPI == 2) {
                    v0 = 0.5f * v0 * (1.0f + erff(v0 * 0.70710678118654752f));
                    v1 = 0.5f * v1 * (1.0f + erff(v1 * 0.70710678118654752f));
                    bf16 h0, l0, h1, l1;
                    bsplit(v0, h0, l0);
                    bsplit(v1, h1, l1);
                    CH[(size_t)row * N + col] = h0;
                    CH[(size_t)row * N + col + 1] = h1;
                    CL[(size_t)row * N + col] = l0;
                    CL[(size_t)row * N + col + 1] = l1;
                } else {
                    float2 o; o.x = v0; o.y = v1;
                    *(float2*)(C + (size_t)row * N + col) = o;
                }
            }
        }
    }
}

// ---------------- fused attention ----------------
__global__ void __launch_bounds__(256)
attn_fused_k(const float* __restrict__ QKV, bf16* __restrict__ OH, bf16* __restrict__ OL) {
    extern __shared__ float sm[];
    float* Ks = sm;                    // [196][KVPAD]
    float* Vs = sm + TT * KVPAD;       // [196][KVPAD]
    __shared__ float Ps[8][TT + 4];

    int bh = blockIdx.x;
    int b = bh / NHEAD, hd = bh % NHEAD;
    int tid = threadIdx.x;
    int warp = tid >> 5, lane = tid & 31;

    const float* Kbase = QKV + (size_t)b * TT * QKVD + DIM + hd * HDIM;
    const float* Vbase = QKV + (size_t)b * TT * QKVD + 2 * DIM + hd * HDIM;

    for (int idx = tid; idx < TT * HDIM; idx += 256) {
        int s = idx >> 6, d = idx & 63;
        Ks[s * KVPAD + d] = Kbase[(size_t)s * QKVD + d];
        Vs[s * KVPAD + d] = Vbase[(size_t)s * QKVD + d];
    }
    __syncthreads();

    for (int t = warp; t < TT; t += 8) {
        const float* qr = QKV + (size_t)(b * TT + t) * QKVD + hd * HDIM;
        float qv[HDIM];
#pragma unroll
        for (int i = 0; i < HDIM / 4; i++) {
            float4 f = *(const float4*)(qr + i * 4);
            qv[i * 4 + 0] = f.x; qv[i * 4 + 1] = f.y;
            qv[i * 4 + 2] = f.z; qv[i * 4 + 3] = f.w;
        }

        float sc[7];
#pragma unroll
        for (int j = 0; j < 7; j++) {
            int s = lane + 32 * j;
            if (s < TT) {
                const float* kr = Ks + s * KVPAD;
                float dot = 0.f;
#pragma unroll
                for (int d = 0; d < HDIM; d++) dot += qv[d] * kr[d];
                sc[j] = dot * 0.125f;
            } else {
                sc[j] = -INFINITY;
            }
        }
        float m = sc[0];
#pragma unroll
        for (int j = 1; j < 7; j++) m = fmaxf(m, sc[j]);
#pragma unroll
        for (int o = 16; o; o >>= 1) m = fmaxf(m, __shfl_xor_sync(0xffffffffu, m, o));
        float sum = 0.f;
        float ex[7];
#pragma unroll
        for (int j = 0; j < 7; j++) {
            ex[j] = (sc[j] == -INFINITY) ? 0.f : __expf(sc[j] - m);
            sum += ex[j];
        }
#pragma unroll
        for (int o = 16; o; o >>= 1) sum += __shfl_xor_sync(0xffffffffu, sum, o);
        float inv = 1.0f / sum;
#pragma unroll
        for (int j = 0; j < 7; j++) {
            int s = lane + 32 * j;
            if (s < TT) Ps[warp][s] = ex[j] * inv;
        }
        __syncwarp();

        float acc0 = 0.f, acc1 = 0.f;
        const float* pw = Ps[warp];
        for (int s = 0; s < TT; s++) {
            float p = pw[s];
            acc0 += p * Vs[s * KVPAD + lane];
            acc1 += p * Vs[s * KVPAD + lane + 32];
        }
        size_t obase = (size_t)(b * TT + t) * DIM + hd * HDIM;
        bf16 h0, l0, h1, l1;
        bsplit(acc0, h0, l0);
        bsplit(acc1, h1, l1);
        OH[obase + lane] = h0;
        OH[obase + lane + 32] = h1;
        OL[obase + lane] = l0;
        OL[obase + lane + 32] = l1;
        __syncwarp();
    }
}

// ---------------- pool + head ----------------
__global__ void pool_k(const float* __restrict__ h, float* __restrict__ pool) {
    int idx = blockIdx.x * blockDim.x + threadIdx.x;
    if (idx >= BVAL * DIM) return;
    int b = idx / DIM, d = idx % DIM;
    float s = 0.f;
    const float* hp = h + (size_t)b * TT * DIM + d;
    for (int t = 0; t < TT; t++) s += hp[(size_t)t * DIM];
    pool[idx] = s * (1.0f / 196.0f);
}

__global__ void head_k(const float* __restrict__ pool, const float* __restrict__ W,
                       float* __restrict__ out) {
    int b = blockIdx.x;
    int tid = threadIdx.x;
    __shared__ float pr[DIM];
    for (int i = tid; i < DIM; i += 256) pr[i] = pool[b * DIM + i];
    __syncthreads();
    for (int n = tid; n < NCLS; n += 256) {
        float acc = 0.f;
        for (int k = 0; k < DIM; k++) acc += pr[k] * W[(size_t)k * NCLS + n];
        out[b * NCLS + n] = acc;
    }
}

// ---------------- launch ----------------
extern "C" void kernel_launch(void* const* d_in, const int* in_sizes, int n_in,
                              void* d_out, int out_size) {
    const float* x       = (const float*)d_in[0];
    const float* embed_W = (const float*)d_in[1];
    const float* embed_b = (const float*)d_in[2];
    const float* Wq      = (const float*)d_in[3];
    const float* Wk      = (const float*)d_in[4];
    const float* Wv      = (const float*)d_in[5];
    const float* Wo      = (const float*)d_in[6];
    const float* bo      = (const float*)d_in[7];
    const float* ln1_g   = (const float*)d_in[8];
    const float* ln1_b   = (const float*)d_in[9];
    const float* ln2_g   = (const float*)d_in[10];
    const float* ln2_b   = (const float*)d_in[11];
    const float* W1      = (const float*)d_in[12];
    const float* b1      = (const float*)d_in[13];
    const float* W2      = (const float*)d_in[14];
    const float* b2      = (const float*)d_in[15];
    const float* head_W  = (const float*)d_in[16];
    float* out = (float*)d_out;

    float *h, *qkv, *pos, *pool;
    cudaGetSymbolAddress((void**)&h,    g_h);
    cudaGetSymbolAddress((void**)&qkv,  g_qkv);
    cudaGetSymbolAddress((void**)&pos,  g_pos);
    cudaGetSymbolAddress((void**)&pool, g_pool);

    bf16 *PH, *PL, *xnH, *xnL, *atH, *atL, *m1H, *m1L;
    bf16 *embH, *embL, *qkvH, *qkvL, *woH, *woL, *w1H, *w1L, *w2H, *w2L;
    cudaGetSymbolAddress((void**)&PH,   g_PH);
    cudaGetSymbolAddress((void**)&PL,   g_PL);
    cudaGetSymbolAddress((void**)&xnH,  g_xnH);
    cudaGetSymbolAddress((void**)&xnL,  g_xnL);
    cudaGetSymbolAddress((void**)&atH,  g_atH);
    cudaGetSymbolAddress((void**)&atL,  g_atL);
    cudaGetSymbolAddress((void**)&m1H,  g_m1H);
    cudaGetSymbolAddress((void**)&m1L,  g_m1L);
    cudaGetSymbolAddress((void**)&embH, g_embH);
    cudaGetSymbolAddress((void**)&embL, g_embL);
    cudaGetSymbolAddress((void**)&qkvH, g_qkvH);
    cudaGetSymbolAddress((void**)&qkvL, g_qkvL);
    cudaGetSymbolAddress((void**)&woH,  g_woH);
    cudaGetSymbolAddress((void**)&woL,  g_woL);
    cudaGetSymbolAddress((void**)&w1H,  g_w1H);
    cudaGetSymbolAddress((void**)&w1L,  g_w1L);
    cudaGetSymbolAddress((void**)&w2H,  g_w2H);
    cudaGetSymbolAddress((void**)&w2L,  g_w2L);

    const int ATTN_SMEM = 2 * TT * KVPAD * sizeof(float);   // ~102 KB
    cudaFuncSetAttribute(attn_fused_k, cudaFuncAttributeMaxDynamicSharedMemorySize,
                         ATTN_SMEM);
    cudaFuncSetAttribute(mma_gemm_bf16<0>, cudaFuncAttributeMaxDynamicSharedMemorySize,
                         GEMM_SMEM);
    cudaFuncSetAttribute(mma_gemm_bf16<1>, cudaFuncAttributeMaxDynamicSharedMemorySize,
                         GEMM_SMEM);
    cudaFuncSetAttribute(mma_gemm_bf16<2>, cudaFuncAttributeMaxDynamicSharedMemorySize,
                         GEMM_SMEM);

    dim3 tb(32, 8);
    dim3 gemb(DIM / 256, MTOK / 128);      // 3 x 49
    dim3 gqkv(QKVD / 256, MTOK / 128);     // 9 x 49
    dim3 gproj(DIM / 256, MTOK / 128);     // 3 x 49
    dim3 gmlp1(MLPD / 256, MTOK / 128);    // 12 x 49

    // launches 1-3 = prep; launch 4 = embed split-GEMM (ncu captures launch #4)
    patchify_split_k<<<(MTOK * PD + 255) / 256, 256>>>(x, PH, PL);
    pos_k<<<(TT * DIM + 255) / 256, 256>>>(pos);
    tsplit_k<<<dim3(DIM / 32, PD / 32, 1), tb>>>(embed_W, embH, embL, PD, DIM);

    mma_gemm_bf16<0><<<gemb, 256, GEMM_SMEM>>>(PH, PL, embH, embL, embed_b, nullptr,
                                               h, nullptr, nullptr, MTOK, DIM, PD);

    addpos_k<<<(MTOK * DIM + 255) / 256, 256>>>(h, pos);
    tsplit_qkv_k<<<dim3(QKVD / 32, DIM / 32, DEPTH), tb>>>(Wq, Wk, Wv, qkvH, qkvL);
    tsplit_k<<<dim3(DIM / 32, DIM / 32, DEPTH), tb>>>(Wo, woH, woL, DIM, DIM);
    tsplit_k<<<dim3(MLPD / 32, DIM / 32, DEPTH), tb>>>(W1, w1H, w1L, DIM, MLPD);
    tsplit_k<<<dim3(DIM / 32, MLPD / 32, DEPTH), tb>>>(W2, w2H, w2L, MLPD, DIM);

    size_t qwsz = (size_t)QKVD * DIM;
    size_t wsz  = (size_t)DIM * DIM;
    size_t msz  = (size_t)DIM * MLPD;

    for (int l = 0; l < DEPTH; l++) {
        ln_k<<<MTOK, 256>>>(h, ln1_g + l * DIM, ln1_b + l * DIM, xnH, xnL);
        mma_gemm_bf16<0><<<gqkv, 256, GEMM_SMEM>>>(xnH, xnL,
            qkvH + (size_t)l * qwsz, qkvL + (size_t)l * qwsz,
            nullptr, nullptr, qkv, nullptr, nullptr, MTOK, QKVD, DIM);
        attn_fused_k<<<BVAL * NHEAD, 256, ATTN_SMEM>>>(qkv, atH, atL);
        mma_gemm_bf16<1><<<gproj, 256, GEMM_SMEM>>>(atH, atL,
            woH + (size_t)l * wsz, woL + (size_t)l * wsz,
            bo + l * DIM, h, h, nullptr, nullptr, MTOK, DIM, DIM);
        ln_k<<<MTOK, 256>>>(h, ln2_g + l * DIM, ln2_b + l * DIM, xnH, xnL);
        mma_gemm_bf16<2><<<gmlp1, 256, GEMM_SMEM>>>(xnH, xnL,
            w1H + (size_t)l * msz, w1L + (size_t)l * msz,
            b1 + l * MLPD, nullptr, nullptr, m1H, m1L, MTOK, MLPD, DIM);
        mma_gemm_bf16<1><<<gproj, 256, GEMM_SMEM>>>(m1H, m1L,
            w2H + (size_t)l * msz, w2L + (size_t)l * msz,
            b2 + l * DIM, h, h, nullptr, nullptr, MTOK, DIM, MLPD);
    }

    pool_k<<<(BVAL * DIM + 255) / 256, 256>>>(h, pool);
    head_k<<<BVAL, 256>>>(pool, head_W, out);
}